// round 6
// baseline (speedup 1.0000x reference)
#include <cuda_runtime.h>
#include <cstdint>

#define N_NODES 50000
#define N_EDGES 400000
#define N_PATHS 512
#define DIM 64

// ---------------- device scratch (static: no runtime allocation) ----------------
__device__ float g_deg[N_NODES];
__device__ float g_agg0[N_NODES * DIM];          // 12.8 MB
__device__ float g_agg1[N_NODES * DIM];          // 12.8 MB
__device__ float g_h0[N_NODES * DIM];            // 12.8 MB
__device__ float g_h1[N_NODES * DIM];            // 12.8 MB
__device__ float g_path[N_PATHS * DIM];          // 128 KB
__device__ int   g_is32;

// ---------------- common helpers ----------------
__device__ __forceinline__ unsigned f2tf32(float f) {
    unsigned u;
    asm("cvt.rna.tf32.f32 %0, %1;" : "=r"(u) : "f"(f));
    return u;
}

__device__ __forceinline__ void mma8(float* c, const unsigned* a, unsigned b0, unsigned b1) {
    asm volatile(
        "mma.sync.aligned.m16n8k8.row.col.f32.tf32.tf32.f32 "
        "{%0,%1,%2,%3}, {%4,%5,%6,%7}, {%8,%9}, {%0,%1,%2,%3};"
        : "+f"(c[0]), "+f"(c[1]), "+f"(c[2]), "+f"(c[3])
        : "r"(a[0]), "r"(a[1]), "r"(a[2]), "r"(a[3]), "r"(b0), "r"(b1));
}

// on-the-fly edge index fetch (handles int32 or int64 payload)
__device__ __forceinline__ void load_edge(const void* ei, int flag, int e,
                                          int& s, int& d) {
    if (flag) {
        const int* p = (const int*)ei;
        s = __ldg(&p[e]);
        d = __ldg(&p[N_EDGES + e]);
    } else {
        const long long* p = (const long long*)ei;
        s = (int)__ldg(&p[e]);
        d = (int)__ldg(&p[N_EDGES + e]);
    }
}

// ---------------- launch 1: fused init (zero scratch) + dtype probe (block 0) ----------------
__global__ void init_kernel(float* __restrict__ deg, float* __restrict__ agg0,
                            float* __restrict__ agg1, float* __restrict__ pemb,
                            int* __restrict__ flag, const int* __restrict__ ei_w) {
    int i = blockIdx.x * blockDim.x + threadIdx.x;
    if (i < N_NODES) deg[i] = 0.0f;
    if (i < N_NODES * DIM) { agg0[i] = 0.0f; agg1[i] = 0.0f; }
    if (i < N_PATHS * DIM) pemb[i] = 0.0f;
    if (blockIdx.x == 0) {
        int t = threadIdx.x;
        int nz = 0;
#pragma unroll
        for (int k = 0; k < 16; k++) {
            int idx = t * 16 + k;  // 4096 probed entries
            if (ei_w[2 * idx + 1] != 0) nz = 1;
        }
        int any = __syncthreads_or(nz);
        if (t == 0) *flag = any;
    }
}

// ---------------- scatter-sum: agg[dst] += x[src]; optional degree count ----------------
template <bool WITH_DEG>
__global__ void scatter_kernel(const float* __restrict__ x,
                               const void* __restrict__ ei,
                               const int* __restrict__ flagp,
                               float* __restrict__ agg,
                               float* __restrict__ deg) {
    int idx = blockIdx.x * blockDim.x + threadIdx.x;
    if (idx >= N_EDGES * 16) return;
    int e = idx >> 4;
    int j = idx & 15;
    int flag = *flagp;
    int s, d;
    load_edge(ei, flag, e, s, d);
    if (WITH_DEG && j == 0) atomicAdd(&deg[d], 1.0f);
    float4 v = __ldg((const float4*)x + (size_t)s * 16 + j);
    atomicAdd((float4*)agg + (size_t)d * 16 + j, v);
}

// ---------------- SAGE layer via tf32 mma: h = relu([agg/deg, x] @ [Wl;Wr] + bl) ----------------
#define SAGE_AX_STRIDE 132
#define SAGE_W_STRIDE 72
#define SAGE_SMEM_BYTES ((128 * SAGE_AX_STRIDE + 128 * SAGE_W_STRIDE) * 4)

__global__ void __launch_bounds__(256) sage_mma_kernel(
    const float* __restrict__ agg, const float* __restrict__ deg,
    const float* __restrict__ x, const float* __restrict__ Wl,
    const float* __restrict__ Wr, const float* __restrict__ bl,
    float* __restrict__ h) {
    extern __shared__ float sm[];
    float* sAX = sm;
    float* sW  = sm + 128 * SAGE_AX_STRIDE;

    int tid = threadIdx.x;
    int lane = tid & 31;
    int warp = tid >> 5;

    for (int i = tid; i < 1024; i += 256) {
        int k = i >> 4, c4 = i & 15;
        float4 wl = ((const float4*)Wl)[i];
        float4 wr = ((const float4*)Wr)[i];
        *(float4*)&sW[k * SAGE_W_STRIDE + c4 * 4] = wl;
        *(float4*)&sW[(k + 64) * SAGE_W_STRIDE + c4 * 4] = wr;
    }

    int bc = (lane & 3) * 2;
    float bias0[8], bias1[8];
#pragma unroll
    for (int ni = 0; ni < 8; ni++) {
        bias0[ni] = __ldg(&bl[ni * 8 + bc]);
        bias1[ni] = __ldg(&bl[ni * 8 + bc + 1]);
    }

    int ntiles = (N_NODES + 127) / 128;
    for (int t = blockIdx.x; t < ntiles; t += gridDim.x) {
        int base = t * 128;
        __syncthreads();
        for (int i = tid; i < 2048; i += 256) {
            int r = i >> 4, c4 = i & 15;
            int row = base + r;
            float4 va = make_float4(0.f, 0.f, 0.f, 0.f);
            float4 vx = va;
            if (row < N_NODES) {
                va = ((const float4*)agg)[(size_t)row * 16 + c4];
                float iv = 1.0f / fmaxf(deg[row], 1.0f);
                va.x *= iv; va.y *= iv; va.z *= iv; va.w *= iv;
                vx = ((const float4*)x)[(size_t)row * 16 + c4];
            }
            *(float4*)&sAX[r * SAGE_AX_STRIDE + c4 * 4] = va;
            *(float4*)&sAX[r * SAGE_AX_STRIDE + 64 + c4 * 4] = vx;
        }
        __syncthreads();

        float acc[8][4];
#pragma unroll
        for (int ni = 0; ni < 8; ni++) {
            acc[ni][0] = bias0[ni];
            acc[ni][1] = bias1[ni];
            acc[ni][2] = bias0[ni];
            acc[ni][3] = bias1[ni];
        }

        int rb = warp * 16 + (lane >> 2);
        int nb = lane >> 2;
#pragma unroll
        for (int kk = 0; kk < 128; kk += 8) {
            int kA = kk + (lane & 3);
            unsigned a[4];
            a[0] = f2tf32(sAX[rb * SAGE_AX_STRIDE + kA]);
            a[1] = f2tf32(sAX[(rb + 8) * SAGE_AX_STRIDE + kA]);
            a[2] = f2tf32(sAX[rb * SAGE_AX_STRIDE + kA + 4]);
            a[3] = f2tf32(sAX[(rb + 8) * SAGE_AX_STRIDE + kA + 4]);
#pragma unroll
            for (int ni = 0; ni < 8; ni++) {
                unsigned b0 = f2tf32(sW[kA * SAGE_W_STRIDE + ni * 8 + nb]);
                unsigned b1 = f2tf32(sW[(kA + 4) * SAGE_W_STRIDE + ni * 8 + nb]);
                mma8(acc[ni], a, b0, b1);
            }
        }

        int r0 = base + rb;
#pragma unroll
        for (int ni = 0; ni < 8; ni++) {
            int col = ni * 8 + bc;
            if (r0 < N_NODES) {
                float2 o = make_float2(fmaxf(acc[ni][0], 0.f), fmaxf(acc[ni][1], 0.f));
                *(float2*)&h[(size_t)r0 * 64 + col] = o;
            }
            if (r0 + 8 < N_NODES) {
                float2 o = make_float2(fmaxf(acc[ni][2], 0.f), fmaxf(acc[ni][3], 0.f));
                *(float2*)&h[(size_t)(r0 + 8) * 64 + col] = o;
            }
        }
    }
}

// ---------------- big GEMM (legacy mma.sync tf32, lean fragment economy) ----------------
// path_emb[512,64] += path_masks[512,K] @ B[K,64], B[k,:] = (h1[src[k]]+h1[dst[k]])*0.5
// 8 warps x 64 rows each (4 m16 tiles). A fed as raw fp32 bits (HW tf32 truncation,
// no cvt in the mainloop); B converted once (cvt.rna) during the fused gather.
#define SA_STRIDE 36
#define SB_STRIDE 72
#define SA_FLOATS (512 * SA_STRIDE)                 // 18432 floats = 72 KB
#define SB_FLOATS (32 * SB_STRIDE)                  // 2304 floats = 9 KB
#define BUF_FLOATS (SA_FLOATS + SB_FLOATS)          // 20736
#define GEMM_SMEM_BYTES (2 * BUF_FLOATS * 4)        // 165888

__device__ __forceinline__ void cp16(float* sdst, const float* gsrc) {
    unsigned s = (unsigned)__cvta_generic_to_shared(sdst);
    asm volatile("cp.async.cg.shared.global [%0], [%1], 16;" ::"r"(s), "l"(gsrc));
}

// A chunk: 512 rows x 32 k = 4096 float4, 256 threads -> 16 each
__device__ __forceinline__ void load_chunk_A(float* sA, const float* __restrict__ A,
                                             int k0, int tid) {
#pragma unroll
    for (int i = 0; i < 16; i++) {
        int f = i * 256 + tid;
        int row = f >> 3;
        int c4 = f & 7;
        cp16(sA + row * SA_STRIDE + c4 * 4,
             A + (size_t)row * N_EDGES + k0 + c4 * 4);
    }
}

// B chunk: 32 edges x 64 n; thread handles edge (tid>>3), n-range (tid&7)*8..+7
__device__ __forceinline__ void gather_chunk_B(float* sB, const float* __restrict__ h1,
                                               const void* __restrict__ ei, int flag,
                                               int k0, int tid) {
    int el = tid >> 3;
    int n0 = (tid & 7) * 8;
    int s, d;
    load_edge(ei, flag, k0 + el, s, d);
    const float4* ps = (const float4*)(h1 + (size_t)s * 64 + n0);
    const float4* pd = (const float4*)(h1 + (size_t)d * 64 + n0);
    float4 a0 = __ldg(ps), a1 = __ldg(ps + 1);
    float4 b0 = __ldg(pd), b1 = __ldg(pd + 1);
    unsigned o[8];
    o[0] = f2tf32((a0.x + b0.x) * 0.5f);
    o[1] = f2tf32((a0.y + b0.y) * 0.5f);
    o[2] = f2tf32((a0.z + b0.z) * 0.5f);
    o[3] = f2tf32((a0.w + b0.w) * 0.5f);
    o[4] = f2tf32((a1.x + b1.x) * 0.5f);
    o[5] = f2tf32((a1.y + b1.y) * 0.5f);
    o[6] = f2tf32((a1.z + b1.z) * 0.5f);
    o[7] = f2tf32((a1.w + b1.w) * 0.5f);
    unsigned* dst = (unsigned*)&sB[el * SB_STRIDE + n0];
    *(uint4*)dst = make_uint4(o[0], o[1], o[2], o[3]);
    *(uint4*)(dst + 4) = make_uint4(o[4], o[5], o[6], o[7]);
}

__global__ void __launch_bounds__(256, 1) path_gemm_kernel(
    const float* __restrict__ A, const float* __restrict__ h1,
    const void* __restrict__ ei, const int* __restrict__ flagp,
    float* __restrict__ C) {
    extern __shared__ float sm[];
    float* bufA[2] = {sm, sm + BUF_FLOATS};
    float* bufB[2] = {sm + SA_FLOATS, sm + BUF_FLOATS + SA_FLOATS};

    int tid = threadIdx.x;
    int lane = tid & 31;
    int warp = tid >> 5;
    int m0 = warp * 64;   // 8 warps x 64 rows
    int flag = *flagp;

    const int nch = N_EDGES / 32;  // 12500
    int c0 = (int)(((long long)blockIdx.x * nch) / gridDim.x);
    int c1 = (int)(((long long)(blockIdx.x + 1) * nch) / gridDim.x);

    float acc[4][8][4] = {};  // 4 m-tiles x 8 n-tiles x 4

    // prologue: stage chunk c0 into buffer 0
    load_chunk_A(bufA[0], A, c0 * 32, tid);
    asm volatile("cp.async.commit_group;");
    gather_chunk_B(bufB[0], h1, ei, flag, c0 * 32, tid);

    int buf = 0;
    for (int c = c0; c < c1; ++c) {
        asm volatile("cp.async.wait_group 0;");
        __syncthreads();  // chunk c fully staged; previous compute done (WAR safe)

        if (c + 1 < c1) {
            load_chunk_A(bufA[buf ^ 1], A, (c + 1) * 32, tid);
            asm volatile("cp.async.commit_group;");
            gather_chunk_B(bufB[buf ^ 1], h1, ei, flag, (c + 1) * 32, tid);
        }

        const float* cA = bufA[buf];
        const float* cB = bufB[buf];
        int rb = m0 + (lane >> 2);
        int nb = lane >> 2;
#pragma unroll
        for (int kk = 0; kk < 32; kk += 8) {
            int kA = kk + (lane & 3);
            unsigned a[4][4];
#pragma unroll
            for (int mt = 0; mt < 4; mt++) {
                int r = rb + mt * 16;
                a[mt][0] = __float_as_uint(cA[r * SA_STRIDE + kA]);
                a[mt][1] = __float_as_uint(cA[(r + 8) * SA_STRIDE + kA]);
                a[mt][2] = __float_as_uint(cA[r * SA_STRIDE + kA + 4]);
                a[mt][3] = __float_as_uint(cA[(r + 8) * SA_STRIDE + kA + 4]);
            }
#pragma unroll
            for (int ni = 0; ni < 8; ni++) {
                unsigned b0 = __float_as_uint(cB[kA * SB_STRIDE + ni * 8 + nb]);
                unsigned b1 = __float_as_uint(cB[(kA + 4) * SB_STRIDE + ni * 8 + nb]);
#pragma unroll
                for (int mt = 0; mt < 4; mt++) mma8(acc[mt][ni], a[mt], b0, b1);
            }
        }
        buf ^= 1;
    }

    // epilogue: accumulate C tile with vector L2 reductions
#pragma unroll
    for (int mt = 0; mt < 4; mt++) {
        int row = m0 + mt * 16 + (lane >> 2);
#pragma unroll
        for (int ni = 0; ni < 8; ni++) {
            int col = ni * 8 + 2 * (lane & 3);
            atomicAdd((float2*)&C[row * 64 + col],
                      make_float2(acc[mt][ni][0], acc[mt][ni][1]));
            atomicAdd((float2*)&C[(row + 8) * 64 + col],
                      make_float2(acc[mt][ni][2], acc[mt][ni][3]));
        }
    }
}

// ---------------- readout: out = path_emb @ Wro + bro ----------------
__global__ void readout_kernel(const float* __restrict__ P,
                               const float* __restrict__ W,
                               const float* __restrict__ b,
                               float* __restrict__ out) {
    int p = blockIdx.x;
    int d = threadIdx.x;
    float s = __ldg(&b[d]);
    const float* pr = P + p * 64;
#pragma unroll 16
    for (int k = 0; k < 64; k++) s += __ldg(&pr[k]) * __ldg(&W[k * 64 + d]);
    out[p * 64 + d] = s;
}

// ---------------- launcher ----------------
extern "C" void kernel_launch(void* const* d_in, const int* in_sizes, int n_in,
                              void* d_out, int out_size) {
    (void)in_sizes; (void)n_in; (void)out_size;
    const float* x   = (const float*)d_in[0];
    const void*  ei  = d_in[1];
    const float* pm  = (const float*)d_in[2];
    const float* Wl0 = (const float*)d_in[3];
    const float* Wr0 = (const float*)d_in[4];
    const float* bl0 = (const float*)d_in[5];
    const float* Wl1 = (const float*)d_in[6];
    const float* Wr1 = (const float*)d_in[7];
    const float* bl1 = (const float*)d_in[8];
    const float* Wro = (const float*)d_in[9];
    const float* bro = (const float*)d_in[10];
    float* out       = (float*)d_out;

    float *deg, *agg0, *agg1, *h0, *h1, *pemb;
    int *flag;
    cudaGetSymbolAddress((void**)&deg,  g_deg);
    cudaGetSymbolAddress((void**)&agg0, g_agg0);
    cudaGetSymbolAddress((void**)&agg1, g_agg1);
    cudaGetSymbolAddress((void**)&h0,   g_h0);
    cudaGetSymbolAddress((void**)&h1,   g_h1);
    cudaGetSymbolAddress((void**)&pemb, g_path);
    cudaGetSymbolAddress((void**)&flag, g_is32);

    cudaFuncSetAttribute(path_gemm_kernel,
                         cudaFuncAttributeMaxDynamicSharedMemorySize, GEMM_SMEM_BYTES);
    cudaFuncSetAttribute(sage_mma_kernel,
                         cudaFuncAttributeMaxDynamicSharedMemorySize, SAGE_SMEM_BYTES);

    // 1: fused zero/init + dtype probe
    init_kernel<<<(N_NODES * DIM + 255) / 256, 256>>>(deg, agg0, agg1, pemb, flag,
                                                      (const int*)ei);
    // 2: layer-0 scatter (+degree)
    scatter_kernel<true><<<(N_EDGES * 16 + 255) / 256, 256>>>(x, ei, flag, agg0, deg);
    // 3: layer-0 sage
    sage_mma_kernel<<<391, 256, SAGE_SMEM_BYTES>>>(agg0, deg, x, Wl0, Wr0, bl0, h0);
    // 4: layer-1 scatter
    scatter_kernel<false><<<(N_EDGES * 16 + 255) / 256, 256>>>(h0, ei, flag, agg1, deg);
    // 5: layer-1 sage
    sage_mma_kernel<<<391, 256, SAGE_SMEM_BYTES>>>(agg1, deg, h0, Wl1, Wr1, bl1, h1);
    // 6: big split-K GEMM (lean mma.sync + fused edge-emb gather)
    path_gemm_kernel<<<148, 256, GEMM_SMEM_BYTES>>>(pm, h1, ei, flag, pemb);
    // 7: readout
    readout_kernel<<<N_PATHS, 64>>>(pemb, Wro, bro, out);
}

// round 7
// speedup vs baseline: 1.0393x; 1.0393x over previous
#include <cuda_runtime.h>
#include <cstdint>

#define N_NODES 50000
#define N_EDGES 400000
#define N_PATHS 512
#define DIM 64

// ---------------- device scratch (static: no runtime allocation) ----------------
__device__ float g_deg[N_NODES];
__device__ float g_agg0[N_NODES * DIM];          // 12.8 MB
__device__ float g_agg1[N_NODES * DIM];          // 12.8 MB
__device__ float g_h0[N_NODES * DIM];            // 12.8 MB
__device__ float g_h1[N_NODES * DIM];            // 12.8 MB
__device__ float g_path[N_PATHS * DIM];          // 128 KB
__device__ int   g_is32;

// ---------------- common helpers ----------------
__device__ __forceinline__ unsigned f2tf32(float f) {
    unsigned u;
    asm("cvt.rna.tf32.f32 %0, %1;" : "=r"(u) : "f"(f));
    return u;
}

// pack two fp32 -> f16x2, lo = first arg (even k), hi = second arg (odd k)
__device__ __forceinline__ unsigned pkhalf2(float lo, float hi) {
    unsigned d;
    asm("cvt.rn.f16x2.f32 %0, %1, %2;" : "=r"(d) : "f"(hi), "f"(lo));
    return d;
}

__device__ __forceinline__ void mma8(float* c, const unsigned* a, unsigned b0, unsigned b1) {
    asm volatile(
        "mma.sync.aligned.m16n8k8.row.col.f32.tf32.tf32.f32 "
        "{%0,%1,%2,%3}, {%4,%5,%6,%7}, {%8,%9}, {%0,%1,%2,%3};"
        : "+f"(c[0]), "+f"(c[1]), "+f"(c[2]), "+f"(c[3])
        : "r"(a[0]), "r"(a[1]), "r"(a[2]), "r"(a[3]), "r"(b0), "r"(b1));
}

__device__ __forceinline__ void mma16h(float* c, unsigned a0, unsigned a1,
                                       unsigned a2, unsigned a3,
                                       unsigned b0, unsigned b1) {
    asm volatile(
        "mma.sync.aligned.m16n8k16.row.col.f32.f16.f16.f32 "
        "{%0,%1,%2,%3}, {%4,%5,%6,%7}, {%8,%9}, {%0,%1,%2,%3};"
        : "+f"(c[0]), "+f"(c[1]), "+f"(c[2]), "+f"(c[3])
        : "r"(a0), "r"(a1), "r"(a2), "r"(a3), "r"(b0), "r"(b1));
}

// on-the-fly edge index fetch (handles int32 or int64 payload)
__device__ __forceinline__ void load_edge(const void* ei, int flag, int e,
                                          int& s, int& d) {
    if (flag) {
        const int* p = (const int*)ei;
        s = __ldg(&p[e]);
        d = __ldg(&p[N_EDGES + e]);
    } else {
        const long long* p = (const long long*)ei;
        s = (int)__ldg(&p[e]);
        d = (int)__ldg(&p[N_EDGES + e]);
    }
}

// ---------------- launch 1: fused init (zero scratch) + dtype probe (block 0) ----------------
__global__ void init_kernel(float* __restrict__ deg, float* __restrict__ agg0,
                            float* __restrict__ agg1, float* __restrict__ pemb,
                            int* __restrict__ flag, const int* __restrict__ ei_w) {
    int i = blockIdx.x * blockDim.x + threadIdx.x;
    if (i < N_NODES) deg[i] = 0.0f;
    if (i < N_NODES * DIM) { agg0[i] = 0.0f; agg1[i] = 0.0f; }
    if (i < N_PATHS * DIM) pemb[i] = 0.0f;
    if (blockIdx.x == 0) {
        int t = threadIdx.x;
        int nz = 0;
#pragma unroll
        for (int k = 0; k < 16; k++) {
            int idx = t * 16 + k;  // 4096 probed entries
            if (ei_w[2 * idx + 1] != 0) nz = 1;
        }
        int any = __syncthreads_or(nz);
        if (t == 0) *flag = any;
    }
}

// ---------------- scatter-sum: agg[dst] += x[src]; optional degree count ----------------
template <bool WITH_DEG>
__global__ void scatter_kernel(const float* __restrict__ x,
                               const void* __restrict__ ei,
                               const int* __restrict__ flagp,
                               float* __restrict__ agg,
                               float* __restrict__ deg) {
    int idx = blockIdx.x * blockDim.x + threadIdx.x;
    if (idx >= N_EDGES * 16) return;
    int e = idx >> 4;
    int j = idx & 15;
    int flag = *flagp;
    int s, d;
    load_edge(ei, flag, e, s, d);
    if (WITH_DEG && j == 0) atomicAdd(&deg[d], 1.0f);
    float4 v = __ldg((const float4*)x + (size_t)s * 16 + j);
    atomicAdd((float4*)agg + (size_t)d * 16 + j, v);
}

// ---------------- SAGE layer via tf32 mma: h = relu([agg/deg, x] @ [Wl;Wr] + bl) ----------------
#define SAGE_AX_STRIDE 132
#define SAGE_W_STRIDE 72
#define SAGE_SMEM_BYTES ((128 * SAGE_AX_STRIDE + 128 * SAGE_W_STRIDE) * 4)

__global__ void __launch_bounds__(256) sage_mma_kernel(
    const float* __restrict__ agg, const float* __restrict__ deg,
    const float* __restrict__ x, const float* __restrict__ Wl,
    const float* __restrict__ Wr, const float* __restrict__ bl,
    float* __restrict__ h) {
    extern __shared__ float sm[];
    float* sAX = sm;
    float* sW  = sm + 128 * SAGE_AX_STRIDE;

    int tid = threadIdx.x;
    int lane = tid & 31;
    int warp = tid >> 5;

    for (int i = tid; i < 1024; i += 256) {
        int k = i >> 4, c4 = i & 15;
        float4 wl = ((const float4*)Wl)[i];
        float4 wr = ((const float4*)Wr)[i];
        *(float4*)&sW[k * SAGE_W_STRIDE + c4 * 4] = wl;
        *(float4*)&sW[(k + 64) * SAGE_W_STRIDE + c4 * 4] = wr;
    }

    int bc = (lane & 3) * 2;
    float bias0[8], bias1[8];
#pragma unroll
    for (int ni = 0; ni < 8; ni++) {
        bias0[ni] = __ldg(&bl[ni * 8 + bc]);
        bias1[ni] = __ldg(&bl[ni * 8 + bc + 1]);
    }

    int ntiles = (N_NODES + 127) / 128;
    for (int t = blockIdx.x; t < ntiles; t += gridDim.x) {
        int base = t * 128;
        __syncthreads();
        for (int i = tid; i < 2048; i += 256) {
            int r = i >> 4, c4 = i & 15;
            int row = base + r;
            float4 va = make_float4(0.f, 0.f, 0.f, 0.f);
            float4 vx = va;
            if (row < N_NODES) {
                va = ((const float4*)agg)[(size_t)row * 16 + c4];
                float iv = 1.0f / fmaxf(deg[row], 1.0f);
                va.x *= iv; va.y *= iv; va.z *= iv; va.w *= iv;
                vx = ((const float4*)x)[(size_t)row * 16 + c4];
            }
            *(float4*)&sAX[r * SAGE_AX_STRIDE + c4 * 4] = va;
            *(float4*)&sAX[r * SAGE_AX_STRIDE + 64 + c4 * 4] = vx;
        }
        __syncthreads();

        float acc[8][4];
#pragma unroll
        for (int ni = 0; ni < 8; ni++) {
            acc[ni][0] = bias0[ni];
            acc[ni][1] = bias1[ni];
            acc[ni][2] = bias0[ni];
            acc[ni][3] = bias1[ni];
        }

        int rb = warp * 16 + (lane >> 2);
        int nb = lane >> 2;
#pragma unroll
        for (int kk = 0; kk < 128; kk += 8) {
            int kA = kk + (lane & 3);
            unsigned a[4];
            a[0] = f2tf32(sAX[rb * SAGE_AX_STRIDE + kA]);
            a[1] = f2tf32(sAX[(rb + 8) * SAGE_AX_STRIDE + kA]);
            a[2] = f2tf32(sAX[rb * SAGE_AX_STRIDE + kA + 4]);
            a[3] = f2tf32(sAX[(rb + 8) * SAGE_AX_STRIDE + kA + 4]);
#pragma unroll
            for (int ni = 0; ni < 8; ni++) {
                unsigned b0 = f2tf32(sW[kA * SAGE_W_STRIDE + ni * 8 + nb]);
                unsigned b1 = f2tf32(sW[(kA + 4) * SAGE_W_STRIDE + ni * 8 + nb]);
                mma8(acc[ni], a, b0, b1);
            }
        }

        int r0 = base + rb;
#pragma unroll
        for (int ni = 0; ni < 8; ni++) {
            int col = ni * 8 + bc;
            if (r0 < N_NODES) {
                float2 o = make_float2(fmaxf(acc[ni][0], 0.f), fmaxf(acc[ni][1], 0.f));
                *(float2*)&h[(size_t)r0 * 64 + col] = o;
            }
            if (r0 + 8 < N_NODES) {
                float2 o = make_float2(fmaxf(acc[ni][2], 0.f), fmaxf(acc[ni][3], 0.f));
                *(float2*)&h[(size_t)(r0 + 8) * 64 + col] = o;
            }
        }
    }
}

// ---------------- big GEMM: fp16 m16n8k16 mma, fp32 accum ----------------
// path_emb[512,64] += path_masks[512,K] @ B[K,64], B[k,:] = (h1[src[k]]+h1[dst[k]])*0.5
// A: fp32 in smem (cp.async), fragments packed to fp16 in-loop (cvt.rn).
// B: gathered + converted to fp16 in smem ([n][k] layout, k-contiguous pairs).
#define SA_STRIDE 36
#define SA_FLOATS (512 * SA_STRIDE)        // 18432 floats = 72 KB per buffer
#define SB_HSTRIDE 40                      // halves per n-row (32 data + 8 pad)
#define SB_HALVES (64 * SB_HSTRIDE)        // 2560 halves = 5120 B per buffer
#define GEMM_SMEM_BYTES (2 * SA_FLOATS * 4 + 2 * SB_HALVES * 2)   // 157696

__device__ __forceinline__ void cp16(float* sdst, const float* gsrc) {
    unsigned s = (unsigned)__cvta_generic_to_shared(sdst);
    asm volatile("cp.async.cg.shared.global [%0], [%1], 16;" ::"r"(s), "l"(gsrc));
}

// A chunk: 512 rows x 32 k = 4096 float4, 512 threads -> 8 each
__device__ __forceinline__ void load_chunk_A(float* sA, const float* __restrict__ A,
                                             int k0, int tid) {
#pragma unroll
    for (int i = 0; i < 8; i++) {
        int f = i * 512 + tid;
        int row = f >> 3;
        int c4 = f & 7;
        cp16(sA + row * SA_STRIDE + c4 * 4,
             A + (size_t)row * N_EDGES + k0 + c4 * 4);
    }
}

__global__ void __launch_bounds__(512, 1) path_gemm_kernel(
    const float* __restrict__ A, const float* __restrict__ h1,
    const void* __restrict__ ei, const int* __restrict__ flagp,
    float* __restrict__ C) {
    extern __shared__ float sm[];
    float* bufA[2] = {sm, sm + SA_FLOATS};
    unsigned short* bufB[2] = {(unsigned short*)(sm + 2 * SA_FLOATS),
                               (unsigned short*)(sm + 2 * SA_FLOATS) + SB_HALVES};

    int tid = threadIdx.x;
    int lane = tid & 31;
    int warp = tid >> 5;
    int m0 = warp * 32;   // 16 warps x 32 rows
    int flag = *flagp;

    // B-gather work split: 256 threads, each handles 2 consecutive edges x 4 n
    int gp = tid & 15;            // edge pair index (edges 2gp, 2gp+1)
    int gn0 = (tid >> 4) * 4;     // n range start (only valid for tid < 256)
    bool gact = (tid < 256);

    const int nch = N_EDGES / 32;  // 12500
    int c0 = (int)(((long long)blockIdx.x * nch) / gridDim.x);
    int c1 = (int)(((long long)(blockIdx.x + 1) * nch) / gridDim.x);

    float acc[2][8][4] = {};

    // ---- prologue: stage chunk c0 into buffer 0 ----
    load_chunk_A(bufA[0], A, c0 * 32, tid);
    asm volatile("cp.async.commit_group;");
    if (gact) {
        int e = c0 * 32 + 2 * gp;
        int s0, d0, s1, d1;
        load_edge(ei, flag, e, s0, d0);
        load_edge(ei, flag, e + 1, s1, d1);
        float4 xs0 = __ldg((const float4*)(h1 + (size_t)s0 * 64 + gn0));
        float4 xd0 = __ldg((const float4*)(h1 + (size_t)d0 * 64 + gn0));
        float4 xs1 = __ldg((const float4*)(h1 + (size_t)s1 * 64 + gn0));
        float4 xd1 = __ldg((const float4*)(h1 + (size_t)d1 * 64 + gn0));
        float v0[4] = {(xs0.x + xd0.x) * 0.5f, (xs0.y + xd0.y) * 0.5f,
                       (xs0.z + xd0.z) * 0.5f, (xs0.w + xd0.w) * 0.5f};
        float v1[4] = {(xs1.x + xd1.x) * 0.5f, (xs1.y + xd1.y) * 0.5f,
                       (xs1.z + xd1.z) * 0.5f, (xs1.w + xd1.w) * 0.5f};
#pragma unroll
        for (int j = 0; j < 4; j++) {
            unsigned pk = pkhalf2(v0[j], v1[j]);
            *(unsigned*)&bufB[0][(gn0 + j) * SB_HSTRIDE + 2 * gp] = pk;
        }
    }
    asm volatile("cp.async.wait_group 0;");
    __syncthreads();

    int buf = 0;
    for (int c = c0; c < c1; ++c) {
        bool more = (c + 1 < c1);
        float4 xs0, xd0, xs1, xd1;
        if (more) {
            load_chunk_A(bufA[buf ^ 1], A, (c + 1) * 32, tid);
            asm volatile("cp.async.commit_group;");
            if (gact) {
                int e = (c + 1) * 32 + 2 * gp;
                int s0, d0, s1, d1;
                load_edge(ei, flag, e, s0, d0);
                load_edge(ei, flag, e + 1, s1, d1);
                xs0 = __ldg((const float4*)(h1 + (size_t)s0 * 64 + gn0));
                xd0 = __ldg((const float4*)(h1 + (size_t)d0 * 64 + gn0));
                xs1 = __ldg((const float4*)(h1 + (size_t)s1 * 64 + gn0));
                xd1 = __ldg((const float4*)(h1 + (size_t)d1 * 64 + gn0));
            }
        }

        // ---- compute chunk c (fp16 mma, K=32 as two k16 steps) ----
        const float* cA = bufA[buf];
        const unsigned short* cB = bufB[buf];
        int rb = m0 + (lane >> 2);
        int nb = lane >> 2;
#pragma unroll
        for (int ks = 0; ks < 2; ks++) {
            int ka = ks * 16 + 2 * (lane & 3);
            unsigned a[2][4];
#pragma unroll
            for (int mt = 0; mt < 2; mt++) {
                int r = rb + mt * 16;
                float2 w0 = *(const float2*)&cA[r * SA_STRIDE + ka];
                float2 w1 = *(const float2*)&cA[(r + 8) * SA_STRIDE + ka];
                float2 w2 = *(const float2*)&cA[r * SA_STRIDE + ka + 8];
                float2 w3 = *(const float2*)&cA[(r + 8) * SA_STRIDE + ka + 8];
                a[mt][0] = pkhalf2(w0.x, w0.y);
                a[mt][1] = pkhalf2(w1.x, w1.y);
                a[mt][2] = pkhalf2(w2.x, w2.y);
                a[mt][3] = pkhalf2(w3.x, w3.y);
            }
#pragma unroll
            for (int ni = 0; ni < 8; ni++) {
                int hoff = (ni * 8 + nb) * SB_HSTRIDE + ks * 16 + 2 * (lane & 3);
                unsigned b0 = *(const unsigned*)&cB[hoff];
                unsigned b1 = *(const unsigned*)&cB[hoff + 8];
                mma16h(acc[0][ni], a[0][0], a[0][1], a[0][2], a[0][3], b0, b1);
                mma16h(acc[1][ni], a[1][0], a[1][1], a[1][2], a[1][3], b0, b1);
            }
        }

        if (more) {
            if (gact) {
                float v0[4] = {(xs0.x + xd0.x) * 0.5f, (xs0.y + xd0.y) * 0.5f,
                               (xs0.z + xd0.z) * 0.5f, (xs0.w + xd0.w) * 0.5f};
                float v1[4] = {(xs1.x + xd1.x) * 0.5f, (xs1.y + xd1.y) * 0.5f,
                               (xs1.z + xd1.z) * 0.5f, (xs1.w + xd1.w) * 0.5f};
#pragma unroll
                for (int j = 0; j < 4; j++) {
                    unsigned pk = pkhalf2(v0[j], v1[j]);
                    *(unsigned*)&bufB[buf ^ 1][(gn0 + j) * SB_HSTRIDE + 2 * gp] = pk;
                }
            }
            asm volatile("cp.async.wait_group 0;");
        }
        __syncthreads();
        buf ^= 1;
    }

    // epilogue: accumulate C tile with vector L2 reductions
#pragma unroll
    for (int mt = 0; mt < 2; mt++) {
        int row = m0 + mt * 16 + (lane >> 2);
#pragma unroll
        for (int ni = 0; ni < 8; ni++) {
            int col = ni * 8 + 2 * (lane & 3);
            atomicAdd((float2*)&C[row * 64 + col],
                      make_float2(acc[mt][ni][0], acc[mt][ni][1]));
            atomicAdd((float2*)&C[(row + 8) * 64 + col],
                      make_float2(acc[mt][ni][2], acc[mt][ni][3]));
        }
    }
}

// ---------------- readout: out = path_emb @ Wro + bro ----------------
__global__ void readout_kernel(const float* __restrict__ P,
                               const float* __restrict__ W,
                               const float* __restrict__ b,
                               float* __restrict__ out) {
    int p = blockIdx.x;
    int d = threadIdx.x;
    float s = __ldg(&b[d]);
    const float* pr = P + p * 64;
#pragma unroll 16
    for (int k = 0; k < 64; k++) s += __ldg(&pr[k]) * __ldg(&W[k * 64 + d]);
    out[p * 64 + d] = s;
}

// ---------------- launcher ----------------
extern "C" void kernel_launch(void* const* d_in, const int* in_sizes, int n_in,
                              void* d_out, int out_size) {
    (void)in_sizes; (void)n_in; (void)out_size;
    const float* x   = (const float*)d_in[0];
    const void*  ei  = d_in[1];
    const float* pm  = (const float*)d_in[2];
    const float* Wl0 = (const float*)d_in[3];
    const float* Wr0 = (const float*)d_in[4];
    const float* bl0 = (const float*)d_in[5];
    const float* Wl1 = (const float*)d_in[6];
    const float* Wr1 = (const float*)d_in[7];
    const float* bl1 = (const float*)d_in[8];
    const float* Wro = (const float*)d_in[9];
    const float* bro = (const float*)d_in[10];
    float* out       = (float*)d_out;

    float *deg, *agg0, *agg1, *h0, *h1, *pemb;
    int *flag;
    cudaGetSymbolAddress((void**)&deg,  g_deg);
    cudaGetSymbolAddress((void**)&agg0, g_agg0);
    cudaGetSymbolAddress((void**)&agg1, g_agg1);
    cudaGetSymbolAddress((void**)&h0,   g_h0);
    cudaGetSymbolAddress((void**)&h1,   g_h1);
    cudaGetSymbolAddress((void**)&pemb, g_path);
    cudaGetSymbolAddress((void**)&flag, g_is32);

    cudaFuncSetAttribute(path_gemm_kernel,
                         cudaFuncAttributeMaxDynamicSharedMemorySize, GEMM_SMEM_BYTES);
    cudaFuncSetAttribute(sage_mma_kernel,
                         cudaFuncAttributeMaxDynamicSharedMemorySize, SAGE_SMEM_BYTES);

    // 1: fused zero/init + dtype probe
    init_kernel<<<(N_NODES * DIM + 255) / 256, 256>>>(deg, agg0, agg1, pemb, flag,
                                                      (const int*)ei);
    // 2: layer-0 scatter (+degree)
    scatter_kernel<true><<<(N_EDGES * 16 + 255) / 256, 256>>>(x, ei, flag, agg0, deg);
    // 3: layer-0 sage
    sage_mma_kernel<<<391, 256, SAGE_SMEM_BYTES>>>(agg0, deg, x, Wl0, Wr0, bl0, h0);
    // 4: layer-1 scatter
    scatter_kernel<false><<<(N_EDGES * 16 + 255) / 256, 256>>>(h0, ei, flag, agg1, deg);
    // 5: layer-1 sage
    sage_mma_kernel<<<391, 256, SAGE_SMEM_BYTES>>>(agg1, deg, h0, Wl1, Wr1, bl1, h1);
    // 6: big split-K GEMM (fp16 m16n8k16 mma + fused edge-emb gather)
    path_gemm_kernel<<<148, 512, GEMM_SMEM_BYTES>>>(pm, h1, ei, flag, pemb);
    // 7: readout
    readout_kernel<<<N_PATHS, 64>>>(pemb, Wro, bro, out);
}